// round 11
// baseline (speedup 1.0000x reference)
#include <cuda_runtime.h>
#include <math.h>

#define MAX_N    16
#define NBINS    4096
#define CAND_MAX 16384
#define HT       1024
#define BPB      18

__device__ unsigned int       g_hist[MAX_N * NBINS];
__device__ unsigned int       g_h16[MAX_N * 65536];   // digit (key>>48) histogram
__device__ int                g_count[MAX_N];
__device__ unsigned int       g_T24[MAX_N];
__device__ unsigned int       g_done1[MAX_N];
__device__ unsigned long long g_cand[MAX_N * CAND_MAX];

__device__ __forceinline__ unsigned int mono_f32(float f) {
    unsigned int u = __float_as_uint(f);
    return (u & 0x80000000u) ? ~u : (u | 0x80000000u);
}
__device__ __forceinline__ float inv_mono(unsigned int m) {
    unsigned int u = (m & 0x80000000u) ? (m & 0x7FFFFFFFu) : ~m;
    return __uint_as_float(u);
}

// Suffix-scan threshold over 4096-bin hist in sh[]. blockDim = 1024; thread t
// owns bins [4t,4t+4). Largest bin with suffix >= st -> *out; suffix strictly
// above it -> *outAbove. Single writer. 2 barriers.
__device__ __forceinline__ void suffix_threshold(const unsigned int* sh,
                                                 unsigned int st,
                                                 unsigned int* warp_tot,
                                                 int* out, unsigned int* outAbove) {
    const int t = threadIdx.x, lane = t & 31, wid = t >> 5;
    unsigned int h0 = sh[t * 4], h1 = sh[t * 4 + 1], h2 = sh[t * 4 + 2], h3 = sh[t * 4 + 3];
    unsigned int seg = h0 + h1 + h2 + h3;
    unsigned int suf = seg;
#pragma unroll
    for (int d = 1; d < 32; d <<= 1) {
        unsigned int v = __shfl_down_sync(0xFFFFFFFFu, suf, d);
        if (lane + d < 32) suf += v;
    }
    if (lane == 0) warp_tot[wid] = suf;
    __syncthreads();
    if (wid == 0) {
        unsigned int wv = warp_tot[lane];
        unsigned int wsuf = wv;
#pragma unroll
        for (int d = 1; d < 32; d <<= 1) {
            unsigned int v = __shfl_down_sync(0xFFFFFFFFu, wsuf, d);
            if (lane + d < 32) wsuf += v;
        }
        warp_tot[lane] = wsuf - wv;
    }
    __syncthreads();
    unsigned int S  = suf + warp_tot[wid];
    unsigned int sN = S - seg;
    unsigned int s3 = sN + h3;
    unsigned int s2 = s3 + h2;
    unsigned int s1 = s2 + h1;
    unsigned int s0 = S;
    if      (s3 >= st && sN < st) { *out = t * 4 + 3; *outAbove = sN; }
    else if (s2 >= st && s3 < st) { *out = t * 4 + 2; *outAbove = s3; }
    else if (s1 >= st && s2 < st) { *out = t * 4 + 1; *outAbove = s2; }
    else if (s0 >= st && s1 < st) { *out = t * 4 + 0; *outAbove = s1; }
}

// ---------------------------------------------------------------------------
// K1: 24-bit sampled threshold (1 block/batch). 16384 strided samples in
// registers; 12-bit coarse + 12-bit sub-bin refine. Zeroes replay state.
// ---------------------------------------------------------------------------
__global__ void __launch_bounds__(1024) sample_thresh_kernel(
        const float* __restrict__ scores, int A, int k) {
    __shared__ unsigned int sh[NBINS];
    __shared__ unsigned int warp_tot[32];
    __shared__ int sT1, sT2;
    __shared__ unsigned int sS1, sDummy;
    const int b = blockIdx.x;
    const int t = threadIdx.x;

    for (int i = t; i < NBINS; i += 1024) { sh[i] = 0; g_hist[b * NBINS + i] = 0; }
    if (t == 0) g_count[b] = 0;
    __syncthreads();

    const size_t base = (size_t)b * (size_t)A;
    const int A4 = A >> 2;

    if ((A & 3) == 0 && A4 >= 4096) {
        const float4* s4 = (const float4*)(scores + base);
        unsigned int m[16];
#pragma unroll
        for (int r = 0; r < 4; r++) {
            int j = t + r * 1024;                          // [0, 4096)
            size_t pos = ((size_t)j * (size_t)A4) >> 12;   // strided over full batch
            float4 v = s4[pos];
            m[r * 4 + 0] = mono_f32(v.x);
            m[r * 4 + 1] = mono_f32(v.y);
            m[r * 4 + 2] = mono_f32(v.z);
            m[r * 4 + 3] = mono_f32(v.w);
        }
#pragma unroll
        for (int q = 0; q < 16; q++) atomicAdd(&sh[m[q] >> 20], 1u);
        __syncthreads();

        long long tgt = (16384LL * 7LL * (long long)k) / (4LL * (long long)A);  // ~3.5k
        if (tgt < 1) tgt = 1;
        if (tgt > 16384) tgt = 16384;
        const unsigned int st = (unsigned)tgt;

        suffix_threshold(sh, st, warp_tot, &sT1, &sS1);
        __syncthreads();
        const int T1 = sT1;
        const unsigned int S1 = sS1;
        __syncthreads();

        for (int i = t; i < NBINS; i += 1024) sh[i] = 0;
        __syncthreads();
#pragma unroll
        for (int q = 0; q < 16; q++)
            if ((int)(m[q] >> 20) == T1) atomicAdd(&sh[(m[q] >> 8) & 0xFFFu], 1u);
        __syncthreads();

        suffix_threshold(sh, st - S1, warp_tot, &sT2, &sDummy);
        __syncthreads();
        if (t == 0) g_T24[b] = ((unsigned)T1 << 12) | (unsigned)sT2;
    } else {
        for (int i = t; i < A; i += 1024)
            atomicAdd(&sh[mono_f32(scores[base + i]) >> 20], 1u);
        __syncthreads();
        suffix_threshold(sh, (unsigned)min(k, A), warp_tot, &sT1, &sS1);
        __syncthreads();
        if (t == 0) g_T24[b] = (unsigned)sT1 << 12;
    }
}

// ---------------------------------------------------------------------------
// warp-aggregated candidate push; also builds the 16-bit digit histogram
// ---------------------------------------------------------------------------
__device__ __forceinline__ void push_warp(int b, bool pred, unsigned long long key) {
    unsigned int bal = __ballot_sync(0xFFFFFFFFu, pred);
    if (!bal) return;
    const int lane = threadIdx.x & 31;
    const int leader = __ffs(bal) - 1;
    int base = 0;
    if (lane == leader) base = atomicAdd(&g_count[b], __popc(bal));
    base = __shfl_sync(0xFFFFFFFFu, base, leader);
    if (pred) {
        int pos = base + __popc(bal & ((1u << lane) - 1u));
        if (pos < CAND_MAX) g_cand[b * CAND_MAX + pos] = key;
        atomicAdd(&g_h16[((size_t)b << 16) + (unsigned)(key >> 48)], 1u);
    }
}

// ---------------------------------------------------------------------------
// K2: single full sweep — compact (m>>8) >= T24. grid (BPB, N) x HT
// ---------------------------------------------------------------------------
__global__ void __launch_bounds__(HT) compact_kernel(
        const float* __restrict__ scores, int A) {
    const int b = blockIdx.y;
    const unsigned int T24 = g_T24[b];
    const size_t base = (size_t)b * (size_t)A;
    const int lane = threadIdx.x & 31;

    if ((A & 3) == 0) {
        const float4* s4 = (const float4*)(scores + base);
        const int A4 = A >> 2;
        const int warp0 = blockIdx.x * (HT / 32) + (threadIdx.x >> 5);
        for (int i0 = warp0 * 32; i0 < A4; i0 += BPB * HT) {
            const int i = i0 + lane;
            const bool in = i < A4;
            float4 v;
            if (in) v = s4[i];
            unsigned int o = (unsigned)(i << 2);
            unsigned int mx = in ? mono_f32(v.x) : 0u;
            unsigned int my = in ? mono_f32(v.y) : 0u;
            unsigned int mz = in ? mono_f32(v.z) : 0u;
            unsigned int mw = in ? mono_f32(v.w) : 0u;
            push_warp(b, in && (mx >> 8) >= T24,
                      ((unsigned long long)mx << 32) | (0xFFFFFFFFu - (o + 0u)));
            push_warp(b, in && (my >> 8) >= T24,
                      ((unsigned long long)my << 32) | (0xFFFFFFFFu - (o + 1u)));
            push_warp(b, in && (mz >> 8) >= T24,
                      ((unsigned long long)mz << 32) | (0xFFFFFFFFu - (o + 2u)));
            push_warp(b, in && (mw >> 8) >= T24,
                      ((unsigned long long)mw << 32) | (0xFFFFFFFFu - (o + 3u)));
        }
    } else {
        const int warp0 = blockIdx.x * (HT / 32) + (threadIdx.x >> 5);
        for (int i0 = warp0 * 32; i0 < A; i0 += BPB * HT) {
            const int i = i0 + lane;
            const bool in = i < A;
            unsigned int m = in ? mono_f32(scores[base + i]) : 0u;
            push_warp(b, in && (m >> 8) >= T24,
                      ((unsigned long long)m << 32) | (0xFFFFFFFFu - (unsigned)i));
        }
    }
}

// ---------------------------------------------------------------------------
// K3 (guarded fallback, ~never runs): exact hist; finisher resets h16/count
// and recompacts alone. grid (BPB, N) x 1024
// ---------------------------------------------------------------------------
__global__ void __launch_bounds__(1024) fb_kernel(
        const float* __restrict__ scores, int A, int k) {
    const int b = blockIdx.y;
    {
        const int c = g_count[b];
        if (c >= min(k, A) && c <= CAND_MAX) return;   // sampled path succeeded
    }
    __shared__ unsigned int sh[NBINS];
    __shared__ unsigned int warp_tot[32];
    __shared__ int sT;
    __shared__ unsigned int sAb;
    __shared__ bool s_last;
    const int t = threadIdx.x;
    const size_t base = (size_t)b * (size_t)A;

    for (int i = t; i < NBINS; i += 1024) sh[i] = 0;
    __syncthreads();
    for (int i = blockIdx.x * 1024 + t; i < A; i += BPB * 1024)
        atomicAdd(&sh[mono_f32(scores[base + i]) >> 20], 1u);
    __syncthreads();
    for (int i = t; i < NBINS; i += 1024) {
        unsigned int c = sh[i];
        if (c) atomicAdd(&g_hist[b * NBINS + i], c);
    }
    __threadfence();
    __syncthreads();
    if (t == 0) s_last = (atomicAdd(&g_done1[b], 1u) == (unsigned)gridDim.x - 1u);
    __syncthreads();
    if (!s_last) return;
    if (t == 0) g_done1[b] = 0;

    for (int i = t; i < NBINS; i += 1024) sh[i] = g_hist[b * NBINS + i];
    __syncthreads();
    suffix_threshold(sh, (unsigned)min(k, A), warp_tot, &sT, &sAb);
    __syncthreads();
    const unsigned int T24 = (unsigned)sT << 12;
    unsigned int* h16 = &g_h16[(size_t)b << 16];
    if (t == 0) { g_T24[b] = T24; g_count[b] = 0; }
    for (int i = t; i < 65536; i += 1024) h16[i] = 0;
    __syncthreads();

    // finisher-only exact recompact (slow path; correctness over speed)
    for (int i = t; i < A; i += 1024) {
        unsigned int m = mono_f32(scores[base + i]);
        if ((m >> 8) >= T24) {
            unsigned long long key = ((unsigned long long)m << 32) |
                                     (unsigned long long)(0xFFFFFFFFu - (unsigned)i);
            int p = atomicAdd(&g_count[b], 1);
            if (p < CAND_MAX) g_cand[b * CAND_MAX + p] = key;
            atomicAdd(&h16[(unsigned)(key >> 48)], 1u);
        }
    }
}

// ---------------------------------------------------------------------------
// K4: counting-sort rank + decode (1 block/batch). Suffix-scan the 64K digit
// histogram, scatter candidates into sorted smem by digit cursor, resolve
// intra-digit ties by direct compare (groups are tiny), decode rank<k rows,
// and reset h16 for the next graph replay. grid N x 1024, dynsmem 128KB.
// ---------------------------------------------------------------------------
__global__ void __launch_bounds__(1024) sort_decode_kernel(
        const float* __restrict__ anchors,
        const float* __restrict__ breg,
        float* __restrict__ out,
        int A, int k) {
    extern __shared__ unsigned long long s_sorted[];   // CAND_MAX entries
    __shared__ unsigned int warp_tot[32];
    const int b = blockIdx.x;
    const int t = threadIdx.x;
    const int lane = t & 31, wid = t >> 5;
    unsigned int* h16 = &g_h16[(size_t)b << 16];
    const int Ct = min(g_count[b], CAND_MAX);

    // ---- phase 1: suffix-scan 64K digit bins; thread t owns [t*64, t*64+64)
    unsigned int hloc[64];
    {
        const uint4* hv = (const uint4*)(h16 + t * 64);
#pragma unroll
        for (int q = 0; q < 16; q++) {
            uint4 v = hv[q];
            hloc[q * 4 + 0] = v.x; hloc[q * 4 + 1] = v.y;
            hloc[q * 4 + 2] = v.z; hloc[q * 4 + 3] = v.w;
        }
    }
    unsigned int csum = 0;
#pragma unroll
    for (int q = 0; q < 64; q++) csum += hloc[q];

    unsigned int suf = csum;                        // inclusive suffix in warp
#pragma unroll
    for (int d = 1; d < 32; d <<= 1) {
        unsigned int v = __shfl_down_sync(0xFFFFFFFFu, suf, d);
        if (lane + d < 32) suf += v;
    }
    if (lane == 0) warp_tot[wid] = suf;
    __syncthreads();
    if (wid == 0) {
        unsigned int wv = warp_tot[lane];
        unsigned int wsuf = wv;
#pragma unroll
        for (int d = 1; d < 32; d <<= 1) {
            unsigned int v = __shfl_down_sync(0xFFFFFFFFu, wsuf, d);
            if (lane + d < 32) wsuf += v;
        }
        warp_tot[lane] = wsuf - wv;                 // strictly-after-warp suffix
    }
    __syncthreads();
    unsigned int acc = (suf - csum) + warp_tot[wid];  // strictly after thread t
    // write S(d) (cursor start) back for nonzero bins, scanning digits downward
#pragma unroll
    for (int q = 63; q >= 0; q--) {
        unsigned int h = hloc[q];
        if (h) h16[t * 64 + q] = acc;
        acc += h;
    }
    __syncthreads();

    // ---- phase 2: scatter candidates into digit-sorted order
    for (int i = t; i < Ct; i += 1024) {
        unsigned long long key = g_cand[(size_t)b * CAND_MAX + i];
        unsigned int d = (unsigned)(key >> 48);
        unsigned int pos = atomicAdd(&h16[d], 1u);
        if (pos < (unsigned)CAND_MAX) s_sorted[pos] = key;
    }
    __syncthreads();

    // ---- phase 3: exact rank via tiny intra-digit scans; decode; reset h16
    const float CLIP = 4.135166556742356f;   // log(1000/16)
    const size_t base = (size_t)b * (size_t)A;
    for (int p = t; p < Ct; p += 1024) {
        unsigned long long key = s_sorted[p];
        unsigned int d = (unsigned)(key >> 48);
        h16[d] = 0;                           // reset for next replay
        int gs = p;
        while (gs > 0 && (unsigned)(s_sorted[gs - 1] >> 48) == d) gs--;
        int r = gs;
        for (int q = gs; q < Ct; q++) {
            unsigned long long kq = s_sorted[q];
            if ((unsigned)(kq >> 48) != d) break;
            r += (kq > key);
        }
        if (r >= k) continue;

        unsigned int idx = 0xFFFFFFFFu - (unsigned int)(key & 0xFFFFFFFFull);
        float sc = inv_mono((unsigned int)(key >> 32));
        size_t g4 = (base + (size_t)idx) * 4;

        float4 box = *(const float4*)(anchors + g4);
        float4 rc  = *(const float4*)(breg + g4);

        float w  = box.z - box.x + 1.0f;
        float h  = box.w - box.y + 1.0f;
        float cx = box.x + 0.5f * w;
        float cy = box.y + 0.5f * h;

        float dw = fminf(rc.z, CLIP);
        float dh = fminf(rc.w, CLIP);

        float pcx = rc.x * w + cx;
        float pcy = rc.y * h + cy;
        float pw  = expf(dw) * w;
        float ph  = expf(dh) * h;

        float* o = out + ((size_t)b * k + r) * 5;
        o[0] = pcx - 0.5f * pw;
        o[1] = pcy - 0.5f * ph;
        o[2] = pcx + 0.5f * pw - 1.0f;
        o[3] = pcy + 0.5f * ph - 1.0f;
        o[4] = sc;
    }
}

// ---------------------------------------------------------------------------
extern "C" void kernel_launch(void* const* d_in, const int* in_sizes, int n_in,
                              void* d_out, int out_size) {
    const float* anchors    = (const float*)d_in[0];
    const float* objectness = (const float*)d_in[1];
    const float* breg       = (const float*)d_in[2];
    float* out = (float*)d_out;

    const int NA = in_sizes[1];
    const int k  = 2000;
    const int N  = out_size / (k * 5);
    const int A  = NA / N;

    static bool attr_set = false;
    if (!attr_set) {
        cudaFuncSetAttribute(sort_decode_kernel,
                             cudaFuncAttributeMaxDynamicSharedMemorySize,
                             CAND_MAX * (int)sizeof(unsigned long long));
        attr_set = true;
    }

    sample_thresh_kernel<<<N, 1024>>>(objectness, A, k);
    compact_kernel<<<dim3(BPB, N), HT>>>(objectness, A);
    fb_kernel<<<dim3(BPB, N), 1024>>>(objectness, A, k);
    sort_decode_kernel<<<N, 1024, CAND_MAX * sizeof(unsigned long long)>>>(
        anchors, breg, out, A, k);
}

// round 12
// speedup vs baseline: 1.1654x; 1.1654x over previous
#include <cuda_runtime.h>
#include <math.h>

#define MAX_N    16
#define NBINS    4096
#define CAND_MAX 16384
#define HT       1024
#define BPB      18
#define RB       32

__device__ unsigned int       g_hist[MAX_N * NBINS];
__device__ unsigned int       g_h16[MAX_N * 65536];   // digit (key>>48) histogram
__device__ int                g_count[MAX_N];
__device__ unsigned int       g_T24[MAX_N];
__device__ unsigned int       g_dstar[MAX_N];         // exact digit trim threshold
__device__ unsigned int       g_done1[MAX_N];
__device__ unsigned int       g_done2[MAX_N];
__device__ int                g_rank[MAX_N * CAND_MAX];  // zero; reset after use
__device__ unsigned long long g_cand[MAX_N * CAND_MAX];

__device__ __forceinline__ unsigned int mono_f32(float f) {
    unsigned int u = __float_as_uint(f);
    return (u & 0x80000000u) ? ~u : (u | 0x80000000u);
}
__device__ __forceinline__ float inv_mono(unsigned int m) {
    unsigned int u = (m & 0x80000000u) ? (m & 0x7FFFFFFFu) : ~m;
    return __uint_as_float(u);
}

// Suffix-scan threshold over 4096-bin hist in sh[]. blockDim = 1024; thread t
// owns bins [4t,4t+4). Largest bin with suffix >= st -> *out; suffix strictly
// above it -> *outAbove. Single writer. 2 barriers.
__device__ __forceinline__ void suffix_threshold(const unsigned int* sh,
                                                 unsigned int st,
                                                 unsigned int* warp_tot,
                                                 int* out, unsigned int* outAbove) {
    const int t = threadIdx.x, lane = t & 31, wid = t >> 5;
    unsigned int h0 = sh[t * 4], h1 = sh[t * 4 + 1], h2 = sh[t * 4 + 2], h3 = sh[t * 4 + 3];
    unsigned int seg = h0 + h1 + h2 + h3;
    unsigned int suf = seg;
#pragma unroll
    for (int d = 1; d < 32; d <<= 1) {
        unsigned int v = __shfl_down_sync(0xFFFFFFFFu, suf, d);
        if (lane + d < 32) suf += v;
    }
    if (lane == 0) warp_tot[wid] = suf;
    __syncthreads();
    if (wid == 0) {
        unsigned int wv = warp_tot[lane];
        unsigned int wsuf = wv;
#pragma unroll
        for (int d = 1; d < 32; d <<= 1) {
            unsigned int v = __shfl_down_sync(0xFFFFFFFFu, wsuf, d);
            if (lane + d < 32) wsuf += v;
        }
        warp_tot[lane] = wsuf - wv;
    }
    __syncthreads();
    unsigned int S  = suf + warp_tot[wid];
    unsigned int sN = S - seg;
    unsigned int s3 = sN + h3;
    unsigned int s2 = s3 + h2;
    unsigned int s1 = s2 + h1;
    unsigned int s0 = S;
    if      (s3 >= st && sN < st) { *out = t * 4 + 3; *outAbove = sN; }
    else if (s2 >= st && s3 < st) { *out = t * 4 + 2; *outAbove = s3; }
    else if (s1 >= st && s2 < st) { *out = t * 4 + 1; *outAbove = s2; }
    else if (s0 >= st && s1 < st) { *out = t * 4 + 0; *outAbove = s1; }
}

// Exact trim threshold from the 64K digit histogram: largest digit d* with
// suffix(d*) >= k. blockDim = 1024; thread t owns digits [64t, 64t+64).
__device__ __forceinline__ void dstar_scan(const unsigned int* h16, unsigned int k,
                                           unsigned int* warp_tot, unsigned int* outD) {
    const int t = threadIdx.x, lane = t & 31, wid = t >> 5;
    unsigned int hl[64];
    unsigned int csum = 0;
    {
        const uint4* hv = (const uint4*)(h16 + t * 64);
#pragma unroll
        for (int q = 0; q < 16; q++) {
            uint4 v = hv[q];
            hl[q * 4 + 0] = v.x; hl[q * 4 + 1] = v.y;
            hl[q * 4 + 2] = v.z; hl[q * 4 + 3] = v.w;
            csum += v.x + v.y + v.z + v.w;
        }
    }
    unsigned int suf = csum;
#pragma unroll
    for (int d = 1; d < 32; d <<= 1) {
        unsigned int v = __shfl_down_sync(0xFFFFFFFFu, suf, d);
        if (lane + d < 32) suf += v;
    }
    if (lane == 0) warp_tot[wid] = suf;
    __syncthreads();
    if (wid == 0) {
        unsigned int wv = warp_tot[lane];
        unsigned int wsuf = wv;
#pragma unroll
        for (int d = 1; d < 32; d <<= 1) {
            unsigned int v = __shfl_down_sync(0xFFFFFFFFu, wsuf, d);
            if (lane + d < 32) wsuf += v;
        }
        warp_tot[lane] = wsuf - wv;
    }
    __syncthreads();
    unsigned int acc = (suf - csum) + warp_tot[wid];   // strictly above thread range
#pragma unroll
    for (int q = 63; q >= 0; q--) {
        unsigned int h = hl[q];
        if (acc < k && acc + h >= k) *outD = (unsigned)(t * 64 + q);
        acc += h;
    }
}

// ---------------------------------------------------------------------------
// K1: 24-bit sampled threshold (1 block/batch). Zeroes replay state.
// ---------------------------------------------------------------------------
__global__ void __launch_bounds__(1024) sample_thresh_kernel(
        const float* __restrict__ scores, int A, int k) {
    __shared__ unsigned int sh[NBINS];
    __shared__ unsigned int warp_tot[32];
    __shared__ int sT1, sT2;
    __shared__ unsigned int sS1, sDummy;
    const int b = blockIdx.x;
    const int t = threadIdx.x;

    for (int i = t; i < NBINS; i += 1024) { sh[i] = 0; g_hist[b * NBINS + i] = 0; }
    if (t == 0) g_count[b] = 0;
    __syncthreads();

    const size_t base = (size_t)b * (size_t)A;
    const int A4 = A >> 2;

    if ((A & 3) == 0 && A4 >= 4096) {
        const float4* s4 = (const float4*)(scores + base);
        unsigned int m[16];
#pragma unroll
        for (int r = 0; r < 4; r++) {
            int j = t + r * 1024;
            size_t pos = ((size_t)j * (size_t)A4) >> 12;
            float4 v = s4[pos];
            m[r * 4 + 0] = mono_f32(v.x);
            m[r * 4 + 1] = mono_f32(v.y);
            m[r * 4 + 2] = mono_f32(v.z);
            m[r * 4 + 3] = mono_f32(v.w);
        }
#pragma unroll
        for (int q = 0; q < 16; q++) atomicAdd(&sh[m[q] >> 20], 1u);
        __syncthreads();

        long long tgt = (16384LL * 7LL * (long long)k) / (4LL * (long long)A);  // ~3.5k
        if (tgt < 1) tgt = 1;
        if (tgt > 16384) tgt = 16384;
        const unsigned int st = (unsigned)tgt;

        suffix_threshold(sh, st, warp_tot, &sT1, &sS1);
        __syncthreads();
        const int T1 = sT1;
        const unsigned int S1 = sS1;
        __syncthreads();

        for (int i = t; i < NBINS; i += 1024) sh[i] = 0;
        __syncthreads();
#pragma unroll
        for (int q = 0; q < 16; q++)
            if ((int)(m[q] >> 20) == T1) atomicAdd(&sh[(m[q] >> 8) & 0xFFFu], 1u);
        __syncthreads();

        suffix_threshold(sh, st - S1, warp_tot, &sT2, &sDummy);
        __syncthreads();
        if (t == 0) g_T24[b] = ((unsigned)T1 << 12) | (unsigned)sT2;
    } else {
        for (int i = t; i < A; i += 1024)
            atomicAdd(&sh[mono_f32(scores[base + i]) >> 20], 1u);
        __syncthreads();
        suffix_threshold(sh, (unsigned)min(k, A), warp_tot, &sT1, &sS1);
        __syncthreads();
        if (t == 0) g_T24[b] = (unsigned)sT1 << 12;
    }
}

// ---------------------------------------------------------------------------
__device__ __forceinline__ void push_warp(int b, bool pred, unsigned long long key) {
    unsigned int bal = __ballot_sync(0xFFFFFFFFu, pred);
    if (!bal) return;
    const int lane = threadIdx.x & 31;
    const int leader = __ffs(bal) - 1;
    int base = 0;
    if (lane == leader) base = atomicAdd(&g_count[b], __popc(bal));
    base = __shfl_sync(0xFFFFFFFFu, base, leader);
    if (pred) {
        int pos = base + __popc(bal & ((1u << lane) - 1u));
        if (pos < CAND_MAX) g_cand[b * CAND_MAX + pos] = key;
        atomicAdd(&g_h16[((size_t)b << 16) + (unsigned)(key >> 48)], 1u);
    }
}

// ---------------------------------------------------------------------------
// K2: single full sweep — compact (m>>8) >= T24 and histogram digits.
// ---------------------------------------------------------------------------
__global__ void __launch_bounds__(HT) compact_kernel(
        const float* __restrict__ scores, int A) {
    const int b = blockIdx.y;
    const unsigned int T24 = g_T24[b];
    const size_t base = (size_t)b * (size_t)A;
    const int lane = threadIdx.x & 31;

    if ((A & 3) == 0) {
        const float4* s4 = (const float4*)(scores + base);
        const int A4 = A >> 2;
        const int warp0 = blockIdx.x * (HT / 32) + (threadIdx.x >> 5);
        for (int i0 = warp0 * 32; i0 < A4; i0 += BPB * HT) {
            const int i = i0 + lane;
            const bool in = i < A4;
            float4 v;
            if (in) v = s4[i];
            unsigned int o = (unsigned)(i << 2);
            unsigned int mx = in ? mono_f32(v.x) : 0u;
            unsigned int my = in ? mono_f32(v.y) : 0u;
            unsigned int mz = in ? mono_f32(v.z) : 0u;
            unsigned int mw = in ? mono_f32(v.w) : 0u;
            push_warp(b, in && (mx >> 8) >= T24,
                      ((unsigned long long)mx << 32) | (0xFFFFFFFFu - (o + 0u)));
            push_warp(b, in && (my >> 8) >= T24,
                      ((unsigned long long)my << 32) | (0xFFFFFFFFu - (o + 1u)));
            push_warp(b, in && (mz >> 8) >= T24,
                      ((unsigned long long)mz << 32) | (0xFFFFFFFFu - (o + 2u)));
            push_warp(b, in && (mw >> 8) >= T24,
                      ((unsigned long long)mw << 32) | (0xFFFFFFFFu - (o + 3u)));
        }
    } else {
        const int warp0 = blockIdx.x * (HT / 32) + (threadIdx.x >> 5);
        for (int i0 = warp0 * 32; i0 < A; i0 += BPB * HT) {
            const int i = i0 + lane;
            const bool in = i < A;
            unsigned int m = in ? mono_f32(scores[base + i]) : 0u;
            push_warp(b, in && (m >> 8) >= T24,
                      ((unsigned long long)m << 32) | (0xFFFFFFFFu - (unsigned)i));
        }
    }
}

// ---------------------------------------------------------------------------
// K3: success path -> block 0 computes exact trim digit d* from h16.
// Fallback (~never): exact hist sweep; finisher re-thresholds, zeroes h16,
// recompacts alone, then computes d*. grid (BPB, N) x 1024
// ---------------------------------------------------------------------------
__global__ void __launch_bounds__(1024) fb_kernel(
        const float* __restrict__ scores, int A, int k) {
    const int b = blockIdx.y;
    const int t = threadIdx.x;
    __shared__ unsigned int warp_tot[32];
    __shared__ unsigned int sD;
    unsigned int* h16 = &g_h16[(size_t)b << 16];

    {
        const int c = g_count[b];
        if (c >= min(k, A) && c <= CAND_MAX) {
            if (blockIdx.x != 0) return;
            dstar_scan(h16, (unsigned)min(k, A), warp_tot, &sD);
            __syncthreads();
            if (t == 0) g_dstar[b] = sD;
            return;
        }
    }
    __shared__ unsigned int sh[NBINS];
    __shared__ int sT;
    __shared__ unsigned int sAb;
    __shared__ bool s_last;
    const size_t base = (size_t)b * (size_t)A;

    for (int i = t; i < NBINS; i += 1024) sh[i] = 0;
    __syncthreads();
    for (int i = blockIdx.x * 1024 + t; i < A; i += BPB * 1024)
        atomicAdd(&sh[mono_f32(scores[base + i]) >> 20], 1u);
    __syncthreads();
    for (int i = t; i < NBINS; i += 1024) {
        unsigned int c = sh[i];
        if (c) atomicAdd(&g_hist[b * NBINS + i], c);
    }
    __threadfence();
    __syncthreads();
    if (t == 0) s_last = (atomicAdd(&g_done1[b], 1u) == (unsigned)gridDim.x - 1u);
    __syncthreads();
    if (!s_last) return;
    if (t == 0) g_done1[b] = 0;

    for (int i = t; i < NBINS; i += 1024) sh[i] = g_hist[b * NBINS + i];
    __syncthreads();
    suffix_threshold(sh, (unsigned)min(k, A), warp_tot, &sT, &sAb);
    __syncthreads();
    const unsigned int T24 = (unsigned)sT << 12;
    if (t == 0) { g_T24[b] = T24; g_count[b] = 0; }
    for (int i = t; i < 65536; i += 1024) h16[i] = 0;
    __syncthreads();

    for (int i = t; i < A; i += 1024) {
        unsigned int m = mono_f32(scores[base + i]);
        if ((m >> 8) >= T24) {
            unsigned long long key = ((unsigned long long)m << 32) |
                                     (unsigned long long)(0xFFFFFFFFu - (unsigned)i);
            int p = atomicAdd(&g_count[b], 1);
            if (p < CAND_MAX) g_cand[b * CAND_MAX + p] = key;
            atomicAdd(&h16[(unsigned)(key >> 48)], 1u);
        }
    }
    __syncthreads();
    dstar_scan(h16, (unsigned)min(k, A), warp_tot, &sD);
    __syncthreads();
    if (t == 0) g_dstar[b] = sD;
}

// ---------------------------------------------------------------------------
// K4: trimmed rank + decode. Candidates with digit >= d* (~k + one group) are
// rank-counted against each other across RB blocks; last block per batch
// decodes and resets g_rank + h16. grid (RB, N) x 1024
// ---------------------------------------------------------------------------
__global__ void __launch_bounds__(1024) rank_decode_kernel(
        const float* __restrict__ anchors,
        const float* __restrict__ breg,
        float* __restrict__ out,
        int A, int k) {
    __shared__ unsigned long long ck[CAND_MAX / RB];   // 512
    __shared__ int s_len;
    __shared__ bool s_last;
    const int b = blockIdx.y;
    const int t = threadIdx.x;
    const int Ct = min(g_count[b], CAND_MAX);
    const unsigned int dstar = g_dstar[b];
    const unsigned long long* cand = &g_cand[(size_t)b * CAND_MAX];
    int* rank = &g_rank[(size_t)b * CAND_MAX];

    const int chunk = (Ct + RB - 1) / RB;
    const int begin = blockIdx.x * chunk;
    int len = Ct - begin;
    if (len > chunk) len = chunk;

    if (t == 0) s_len = 0;
    __syncthreads();
    for (int j = t; j < len; j += 1024) {
        unsigned long long key = cand[begin + j];
        if ((unsigned)(key >> 48) >= dstar) {
            int p = atomicAdd(&s_len, 1);
            ck[p] = key;
        }
    }
    __syncthreads();
    const int flen = s_len;

    if (flen > 0) {
        for (int bi = 0; bi < Ct; bi += 4096) {
            const int i0 = bi + t, i1 = i0 + 1024, i2 = i0 + 2048, i3 = i0 + 3072;
            unsigned long long m0 = ~0ull, m1 = ~0ull, m2 = ~0ull, m3 = ~0ull;
            if (i0 < Ct) { unsigned long long x = cand[i0]; if ((unsigned)(x >> 48) >= dstar) m0 = x; }
            if (i1 < Ct) { unsigned long long x = cand[i1]; if ((unsigned)(x >> 48) >= dstar) m1 = x; }
            if (i2 < Ct) { unsigned long long x = cand[i2]; if ((unsigned)(x >> 48) >= dstar) m2 = x; }
            if (i3 < Ct) { unsigned long long x = cand[i3]; if ((unsigned)(x >> 48) >= dstar) m3 = x; }
            int c0 = 0, c1 = 0, c2 = 0, c3 = 0;
            for (int j = 0; j < flen; j++) {
                unsigned long long kj = ck[j];
                c0 += (kj > m0);
                c1 += (kj > m1);
                c2 += (kj > m2);
                c3 += (kj > m3);
            }
            if (i0 < Ct && c0) atomicAdd(&rank[i0], c0);
            if (i1 < Ct && c1) atomicAdd(&rank[i1], c1);
            if (i2 < Ct && c2) atomicAdd(&rank[i2], c2);
            if (i3 < Ct && c3) atomicAdd(&rank[i3], c3);
        }
    }
    __threadfence();
    __syncthreads();
    if (t == 0) s_last = (atomicAdd(&g_done2[b], 1u) == (unsigned)gridDim.x - 1u);
    __syncthreads();
    if (!s_last) return;
    if (t == 0) g_done2[b] = 0;

    // ---- finisher: decode trimmed candidates with rank < k; reset state ----
    unsigned int* h16 = &g_h16[(size_t)b << 16];
    const float CLIP = 4.135166556742356f;   // log(1000/16)
    const size_t base = (size_t)b * (size_t)A;
    for (int i = t; i < Ct; i += 1024) {
        const unsigned long long key = cand[i];
        const unsigned int d = (unsigned)(key >> 48);
        h16[d] = 0;                           // reset digit histogram
        const int r = rank[i];
        rank[i] = 0;                          // reset ranks
        if (d < dstar || r >= k) continue;

        unsigned int idx = 0xFFFFFFFFu - (unsigned int)(key & 0xFFFFFFFFull);
        float sc = inv_mono((unsigned int)(key >> 32));
        size_t g4 = (base + (size_t)idx) * 4;

        float4 box = *(const float4*)(anchors + g4);
        float4 rc  = *(const float4*)(breg + g4);

        float w  = box.z - box.x + 1.0f;
        float h  = box.w - box.y + 1.0f;
        float cx = box.x + 0.5f * w;
        float cy = box.y + 0.5f * h;

        float dw = fminf(rc.z, CLIP);
        float dh = fminf(rc.w, CLIP);

        float pcx = rc.x * w + cx;
        float pcy = rc.y * h + cy;
        float pw  = expf(dw) * w;
        float ph  = expf(dh) * h;

        float* o = out + ((size_t)b * k + r) * 5;
        o[0] = pcx - 0.5f * pw;
        o[1] = pcy - 0.5f * ph;
        o[2] = pcx + 0.5f * pw - 1.0f;
        o[3] = pcy + 0.5f * ph - 1.0f;
        o[4] = sc;
    }
}

// ---------------------------------------------------------------------------
extern "C" void kernel_launch(void* const* d_in, const int* in_sizes, int n_in,
                              void* d_out, int out_size) {
    const float* anchors    = (const float*)d_in[0];
    const float* objectness = (const float*)d_in[1];
    const float* breg       = (const float*)d_in[2];
    float* out = (float*)d_out;

    const int NA = in_sizes[1];
    const int k  = 2000;
    const int N  = out_size / (k * 5);
    const int A  = NA / N;

    sample_thresh_kernel<<<N, 1024>>>(objectness, A, k);
    compact_kernel<<<dim3(BPB, N), HT>>>(objectness, A);
    fb_kernel<<<dim3(BPB, N), 1024>>>(objectness, A, k);
    rank_decode_kernel<<<dim3(RB, N), 1024>>>(anchors, breg, out, A, k);
}

// round 13
// speedup vs baseline: 1.2709x; 1.0904x over previous
#include <cuda_runtime.h>
#include <math.h>

#define MAX_N     16
#define NBINS     4096
#define CAND_MAX  16384
#define HT        1024
#define BPB       18
#define TRIM_TILE 4096

__device__ unsigned int       g_hist[MAX_N * NBINS];
__device__ unsigned int       g_h16[MAX_N * 65536];   // digit (key>>48) histogram
__device__ int                g_count[MAX_N];
__device__ int                g_ctrim[MAX_N];
__device__ unsigned int       g_T24[MAX_N];
__device__ unsigned int       g_done1[MAX_N];
__device__ unsigned long long g_cand[MAX_N * CAND_MAX];
__device__ unsigned long long g_trim[MAX_N * CAND_MAX];

__device__ __forceinline__ unsigned int mono_f32(float f) {
    unsigned int u = __float_as_uint(f);
    return (u & 0x80000000u) ? ~u : (u | 0x80000000u);
}
__device__ __forceinline__ float inv_mono(unsigned int m) {
    unsigned int u = (m & 0x80000000u) ? (m & 0x7FFFFFFFu) : ~m;
    return __uint_as_float(u);
}

// Suffix-scan threshold over 4096-bin hist in sh[]. blockDim = 1024; thread t
// owns bins [4t,4t+4). Largest bin with suffix >= st -> *out; suffix strictly
// above it -> *outAbove. Single writer. 2 barriers.
__device__ __forceinline__ void suffix_threshold(const unsigned int* sh,
                                                 unsigned int st,
                                                 unsigned int* warp_tot,
                                                 int* out, unsigned int* outAbove) {
    const int t = threadIdx.x, lane = t & 31, wid = t >> 5;
    unsigned int h0 = sh[t * 4], h1 = sh[t * 4 + 1], h2 = sh[t * 4 + 2], h3 = sh[t * 4 + 3];
    unsigned int seg = h0 + h1 + h2 + h3;
    unsigned int suf = seg;
#pragma unroll
    for (int d = 1; d < 32; d <<= 1) {
        unsigned int v = __shfl_down_sync(0xFFFFFFFFu, suf, d);
        if (lane + d < 32) suf += v;
    }
    if (lane == 0) warp_tot[wid] = suf;
    __syncthreads();
    if (wid == 0) {
        unsigned int wv = warp_tot[lane];
        unsigned int wsuf = wv;
#pragma unroll
        for (int d = 1; d < 32; d <<= 1) {
            unsigned int v = __shfl_down_sync(0xFFFFFFFFu, wsuf, d);
            if (lane + d < 32) wsuf += v;
        }
        warp_tot[lane] = wsuf - wv;
    }
    __syncthreads();
    unsigned int S  = suf + warp_tot[wid];
    unsigned int sN = S - seg;
    unsigned int s3 = sN + h3;
    unsigned int s2 = s3 + h2;
    unsigned int s1 = s2 + h1;
    unsigned int s0 = S;
    if      (s3 >= st && sN < st) { *out = t * 4 + 3; *outAbove = sN; }
    else if (s2 >= st && s3 < st) { *out = t * 4 + 2; *outAbove = s3; }
    else if (s1 >= st && s2 < st) { *out = t * 4 + 1; *outAbove = s2; }
    else if (s0 >= st && s1 < st) { *out = t * 4 + 0; *outAbove = s1; }
}

// Exact trim digit from the 64K digit histogram: largest digit d* with
// suffix(d*) >= k. blockDim = 1024; thread t owns digits [64t, 64t+64).
__device__ __forceinline__ void dstar_scan(const unsigned int* h16, unsigned int k,
                                           unsigned int* warp_tot, unsigned int* outD) {
    const int t = threadIdx.x, lane = t & 31, wid = t >> 5;
    unsigned int hl[64];
    unsigned int csum = 0;
    {
        const uint4* hv = (const uint4*)(h16 + t * 64);
#pragma unroll
        for (int q = 0; q < 16; q++) {
            uint4 v = hv[q];
            hl[q * 4 + 0] = v.x; hl[q * 4 + 1] = v.y;
            hl[q * 4 + 2] = v.z; hl[q * 4 + 3] = v.w;
            csum += v.x + v.y + v.z + v.w;
        }
    }
    unsigned int suf = csum;
#pragma unroll
    for (int d = 1; d < 32; d <<= 1) {
        unsigned int v = __shfl_down_sync(0xFFFFFFFFu, suf, d);
        if (lane + d < 32) suf += v;
    }
    if (lane == 0) warp_tot[wid] = suf;
    __syncthreads();
    if (wid == 0) {
        unsigned int wv = warp_tot[lane];
        unsigned int wsuf = wv;
#pragma unroll
        for (int d = 1; d < 32; d <<= 1) {
            unsigned int v = __shfl_down_sync(0xFFFFFFFFu, wsuf, d);
            if (lane + d < 32) wsuf += v;
        }
        warp_tot[lane] = wsuf - wv;
    }
    __syncthreads();
    unsigned int acc = (suf - csum) + warp_tot[wid];   // strictly above thread range
#pragma unroll
    for (int q = 63; q >= 0; q--) {
        unsigned int h = hl[q];
        if (acc < k && acc + h >= k) *outD = (unsigned)(t * 64 + q);
        acc += h;
    }
}

// ---------------------------------------------------------------------------
// K1: 24-bit sampled threshold (1 block/batch). Zeroes replay state.
// ---------------------------------------------------------------------------
__global__ void __launch_bounds__(1024) sample_thresh_kernel(
        const float* __restrict__ scores, int A, int k) {
    __shared__ unsigned int sh[NBINS];
    __shared__ unsigned int warp_tot[32];
    __shared__ int sT1, sT2;
    __shared__ unsigned int sS1, sDummy;
    const int b = blockIdx.x;
    const int t = threadIdx.x;

    for (int i = t; i < NBINS; i += 1024) { sh[i] = 0; g_hist[b * NBINS + i] = 0; }
    if (t == 0) { g_count[b] = 0; g_ctrim[b] = 0; }
    __syncthreads();

    const size_t base = (size_t)b * (size_t)A;
    const int A4 = A >> 2;

    if ((A & 3) == 0 && A4 >= 4096) {
        const float4* s4 = (const float4*)(scores + base);
        unsigned int m[16];
#pragma unroll
        for (int r = 0; r < 4; r++) {
            int j = t + r * 1024;
            size_t pos = ((size_t)j * (size_t)A4) >> 12;
            float4 v = s4[pos];
            m[r * 4 + 0] = mono_f32(v.x);
            m[r * 4 + 1] = mono_f32(v.y);
            m[r * 4 + 2] = mono_f32(v.z);
            m[r * 4 + 3] = mono_f32(v.w);
        }
#pragma unroll
        for (int q = 0; q < 16; q++) atomicAdd(&sh[m[q] >> 20], 1u);
        __syncthreads();

        long long tgt = (16384LL * 7LL * (long long)k) / (4LL * (long long)A);  // ~3.5k
        if (tgt < 1) tgt = 1;
        if (tgt > 16384) tgt = 16384;
        const unsigned int st = (unsigned)tgt;

        suffix_threshold(sh, st, warp_tot, &sT1, &sS1);
        __syncthreads();
        const int T1 = sT1;
        const unsigned int S1 = sS1;
        __syncthreads();

        for (int i = t; i < NBINS; i += 1024) sh[i] = 0;
        __syncthreads();
#pragma unroll
        for (int q = 0; q < 16; q++)
            if ((int)(m[q] >> 20) == T1) atomicAdd(&sh[(m[q] >> 8) & 0xFFFu], 1u);
        __syncthreads();

        suffix_threshold(sh, st - S1, warp_tot, &sT2, &sDummy);
        __syncthreads();
        if (t == 0) g_T24[b] = ((unsigned)T1 << 12) | (unsigned)sT2;
    } else {
        for (int i = t; i < A; i += 1024)
            atomicAdd(&sh[mono_f32(scores[base + i]) >> 20], 1u);
        __syncthreads();
        suffix_threshold(sh, (unsigned)min(k, A), warp_tot, &sT1, &sS1);
        __syncthreads();
        if (t == 0) g_T24[b] = (unsigned)sT1 << 12;
    }
}

// ---------------------------------------------------------------------------
__device__ __forceinline__ void push_warp(int b, bool pred, unsigned long long key) {
    unsigned int bal = __ballot_sync(0xFFFFFFFFu, pred);
    if (!bal) return;
    const int lane = threadIdx.x & 31;
    const int leader = __ffs(bal) - 1;
    int base = 0;
    if (lane == leader) base = atomicAdd(&g_count[b], __popc(bal));
    base = __shfl_sync(0xFFFFFFFFu, base, leader);
    if (pred) {
        int pos = base + __popc(bal & ((1u << lane) - 1u));
        if (pos < CAND_MAX) g_cand[b * CAND_MAX + pos] = key;
        atomicAdd(&g_h16[((size_t)b << 16) + (unsigned)(key >> 48)], 1u);
    }
}

// ---------------------------------------------------------------------------
// K2: single full sweep — compact (m>>8) >= T24 and histogram digits.
// ---------------------------------------------------------------------------
__global__ void __launch_bounds__(HT) compact_kernel(
        const float* __restrict__ scores, int A) {
    const int b = blockIdx.y;
    const unsigned int T24 = g_T24[b];
    const size_t base = (size_t)b * (size_t)A;
    const int lane = threadIdx.x & 31;

    if ((A & 3) == 0) {
        const float4* s4 = (const float4*)(scores + base);
        const int A4 = A >> 2;
        const int warp0 = blockIdx.x * (HT / 32) + (threadIdx.x >> 5);
        for (int i0 = warp0 * 32; i0 < A4; i0 += BPB * HT) {
            const int i = i0 + lane;
            const bool in = i < A4;
            float4 v;
            if (in) v = s4[i];
            unsigned int o = (unsigned)(i << 2);
            unsigned int mx = in ? mono_f32(v.x) : 0u;
            unsigned int my = in ? mono_f32(v.y) : 0u;
            unsigned int mz = in ? mono_f32(v.z) : 0u;
            unsigned int mw = in ? mono_f32(v.w) : 0u;
            push_warp(b, in && (mx >> 8) >= T24,
                      ((unsigned long long)mx << 32) | (0xFFFFFFFFu - (o + 0u)));
            push_warp(b, in && (my >> 8) >= T24,
                      ((unsigned long long)my << 32) | (0xFFFFFFFFu - (o + 1u)));
            push_warp(b, in && (mz >> 8) >= T24,
                      ((unsigned long long)mz << 32) | (0xFFFFFFFFu - (o + 2u)));
            push_warp(b, in && (mw >> 8) >= T24,
                      ((unsigned long long)mw << 32) | (0xFFFFFFFFu - (o + 3u)));
        }
    } else {
        const int warp0 = blockIdx.x * (HT / 32) + (threadIdx.x >> 5);
        for (int i0 = warp0 * 32; i0 < A; i0 += BPB * HT) {
            const int i = i0 + lane;
            const bool in = i < A;
            unsigned int m = in ? mono_f32(scores[base + i]) : 0u;
            push_warp(b, in && (m >> 8) >= T24,
                      ((unsigned long long)m << 32) | (0xFFFFFFFFu - (unsigned)i));
        }
    }
}

// ---------------------------------------------------------------------------
// shared tail for K3: compute d*, zero h16, compact trimmed keys to g_trim.
// Runs on ONE 1024-thread block per batch.
// ---------------------------------------------------------------------------
__device__ __forceinline__ void trim_finish(int b, int A, int k,
                                            unsigned int* warp_tot,
                                            unsigned int* sD) {
    const int t = threadIdx.x;
    unsigned int* h16 = &g_h16[(size_t)b << 16];
    dstar_scan(h16, (unsigned)min(k, A), warp_tot, sD);
    __syncthreads();
    const unsigned int dstar = *sD;
    for (int i = t; i < 65536; i += 1024) h16[i] = 0;   // reset for next replay

    const int Ct = min(g_count[b], CAND_MAX);
    const unsigned long long* cand = &g_cand[(size_t)b * CAND_MAX];
    unsigned long long* trim = &g_trim[(size_t)b * CAND_MAX];
    const int lane = t & 31;
    for (int i0 = (t & ~31); i0 < Ct; i0 += 1024) {
        const int i = i0 + lane;
        const bool in = i < Ct;
        unsigned long long key = in ? cand[i] : 0ull;
        bool pred = in && (unsigned)(key >> 48) >= dstar;
        unsigned int bal = __ballot_sync(0xFFFFFFFFu, pred);
        if (!bal) continue;
        int basep = 0;
        const int leader = __ffs(bal) - 1;
        if (lane == leader) basep = atomicAdd(&g_ctrim[b], __popc(bal));
        basep = __shfl_sync(0xFFFFFFFFu, basep, leader);
        if (pred) {
            int pos = basep + __popc(bal & ((1u << lane) - 1u));
            if (pos < CAND_MAX) trim[pos] = key;
        }
    }
}

// ---------------------------------------------------------------------------
// K3: success path -> block 0 trims. Fallback (~never): exact hist sweep;
// finisher re-thresholds, recompacts alone, then trims. grid (BPB, N) x 1024
// ---------------------------------------------------------------------------
__global__ void __launch_bounds__(1024) fb_kernel(
        const float* __restrict__ scores, int A, int k) {
    const int b = blockIdx.y;
    const int t = threadIdx.x;
    __shared__ unsigned int warp_tot[32];
    __shared__ unsigned int sD;
    unsigned int* h16 = &g_h16[(size_t)b << 16];

    {
        const int c = g_count[b];
        if (c >= min(k, A) && c <= CAND_MAX) {
            if (blockIdx.x != 0) return;
            trim_finish(b, A, k, warp_tot, &sD);
            return;
        }
    }
    __shared__ unsigned int sh[NBINS];
    __shared__ int sT;
    __shared__ unsigned int sAb;
    __shared__ bool s_last;
    const size_t base = (size_t)b * (size_t)A;

    for (int i = t; i < NBINS; i += 1024) sh[i] = 0;
    __syncthreads();
    for (int i = blockIdx.x * 1024 + t; i < A; i += BPB * 1024)
        atomicAdd(&sh[mono_f32(scores[base + i]) >> 20], 1u);
    __syncthreads();
    for (int i = t; i < NBINS; i += 1024) {
        unsigned int c = sh[i];
        if (c) atomicAdd(&g_hist[b * NBINS + i], c);
    }
    __threadfence();
    __syncthreads();
    if (t == 0) s_last = (atomicAdd(&g_done1[b], 1u) == (unsigned)gridDim.x - 1u);
    __syncthreads();
    if (!s_last) return;
    if (t == 0) g_done1[b] = 0;

    for (int i = t; i < NBINS; i += 1024) sh[i] = g_hist[b * NBINS + i];
    __syncthreads();
    suffix_threshold(sh, (unsigned)min(k, A), warp_tot, &sT, &sAb);
    __syncthreads();
    const unsigned int T24 = (unsigned)sT << 12;
    if (t == 0) { g_T24[b] = T24; g_count[b] = 0; g_ctrim[b] = 0; }
    for (int i = t; i < 65536; i += 1024) h16[i] = 0;
    __syncthreads();

    for (int i = t; i < A; i += 1024) {
        unsigned int m = mono_f32(scores[base + i]);
        if ((m >> 8) >= T24) {
            unsigned long long key = ((unsigned long long)m << 32) |
                                     (unsigned long long)(0xFFFFFFFFu - (unsigned)i);
            int p = atomicAdd(&g_count[b], 1);
            if (p < CAND_MAX) g_cand[b * CAND_MAX + p] = key;
            atomicAdd(&h16[(unsigned)(key >> 48)], 1u);
        }
    }
    __syncthreads();
    trim_finish(b, A, k, warp_tot, &sD);
}

// ---------------------------------------------------------------------------
// K4: warp-per-candidate rank + decode over the trimmed set (ranks within the
// trimmed set are exact global ranks). grid (16, N) x 512, 32 KB static smem.
// ---------------------------------------------------------------------------
__global__ void __launch_bounds__(512) rank_decode_kernel(
        const float* __restrict__ anchors,
        const float* __restrict__ breg,
        float* __restrict__ out,
        int A, int k) {
    __shared__ unsigned long long tile[TRIM_TILE];
    const int b = blockIdx.y;
    const int t = threadIdx.x;
    const int lane = t & 31;
    const int gw = blockIdx.x * (512 / 32) + (t >> 5);   // global warp id, 0..255
    const int NW = gridDim.x * (512 / 32);               // 256 warps per batch
    const int Ctr = min(g_ctrim[b], CAND_MAX);
    const unsigned long long* trim = &g_trim[(size_t)b * CAND_MAX];

    const float CLIP = 4.135166556742356f;   // log(1000/16)
    const size_t base = (size_t)b * (size_t)A;

    const bool fits = (Ctr <= TRIM_TILE);
    if (fits) {
        for (int i = t; i < Ctr; i += 512) tile[i] = trim[i];
        __syncthreads();
    }
    const unsigned long long* keys = fits ? tile : trim;

    for (int c = gw; c < Ctr; c += NW) {
        const unsigned long long key = keys[c];
        int r = 0;
        for (int j = lane; j < Ctr; j += 32) r += (keys[j] > key);
#pragma unroll
        for (int d = 16; d >= 1; d >>= 1)
            r += __shfl_down_sync(0xFFFFFFFFu, r, d);
        r = __shfl_sync(0xFFFFFFFFu, r, 0);
        if (r >= k || lane != 0) continue;

        unsigned int idx = 0xFFFFFFFFu - (unsigned int)(key & 0xFFFFFFFFull);
        float sc = inv_mono((unsigned int)(key >> 32));
        size_t g4 = (base + (size_t)idx) * 4;

        float4 box = *(const float4*)(anchors + g4);
        float4 rc  = *(const float4*)(breg + g4);

        float w  = box.z - box.x + 1.0f;
        float h  = box.w - box.y + 1.0f;
        float cx = box.x + 0.5f * w;
        float cy = box.y + 0.5f * h;

        float dw = fminf(rc.z, CLIP);
        float dh = fminf(rc.w, CLIP);

        float pcx = rc.x * w + cx;
        float pcy = rc.y * h + cy;
        float pw  = expf(dw) * w;
        float ph  = expf(dh) * h;

        float* o = out + ((size_t)b * k + r) * 5;
        o[0] = pcx - 0.5f * pw;
        o[1] = pcy - 0.5f * ph;
        o[2] = pcx + 0.5f * pw - 1.0f;
        o[3] = pcy + 0.5f * ph - 1.0f;
        o[4] = sc;
    }
}

// ---------------------------------------------------------------------------
extern "C" void kernel_launch(void* const* d_in, const int* in_sizes, int n_in,
                              void* d_out, int out_size) {
    const float* anchors    = (const float*)d_in[0];
    const float* objectness = (const float*)d_in[1];
    const float* breg       = (const float*)d_in[2];
    float* out = (float*)d_out;

    const int NA = in_sizes[1];
    const int k  = 2000;
    const int N  = out_size / (k * 5);
    const int A  = NA / N;

    sample_thresh_kernel<<<N, 1024>>>(objectness, A, k);
    compact_kernel<<<dim3(BPB, N), HT>>>(objectness, A);
    fb_kernel<<<dim3(BPB, N), 1024>>>(objectness, A, k);
    rank_decode_kernel<<<dim3(16, N), 512>>>(anchors, breg, out, A, k);
}

// round 14
// speedup vs baseline: 1.3958x; 1.0983x over previous
#include <cuda_runtime.h>
#include <math.h>

#define MAX_N     16
#define NBINS     4096
#define CAND_MAX  16384
#define HT        1024
#define BPB       18
#define TRIM_TILE 4096

__device__ unsigned int       g_hist[MAX_N * NBINS];
__device__ unsigned int       g_h16[MAX_N * 65536];   // digit (key>>48) histogram
__device__ int                g_count[MAX_N];
__device__ int                g_ctrim[MAX_N];
__device__ unsigned int       g_T24[MAX_N];
__device__ unsigned int       g_done1[MAX_N];
__device__ unsigned long long g_cand[MAX_N * CAND_MAX];
__device__ unsigned long long g_trim[MAX_N * CAND_MAX];

__device__ __forceinline__ unsigned int mono_f32(float f) {
    unsigned int u = __float_as_uint(f);
    return (u & 0x80000000u) ? ~u : (u | 0x80000000u);
}
__device__ __forceinline__ float inv_mono(unsigned int m) {
    unsigned int u = (m & 0x80000000u) ? (m & 0x7FFFFFFFu) : ~m;
    return __uint_as_float(u);
}

// Suffix-scan threshold over 4096-bin hist in sh[]. blockDim = 1024; thread t
// owns bins [4t,4t+4). Largest bin with suffix >= st -> *out; suffix strictly
// above it -> *outAbove. Single writer. 2 barriers.
__device__ __forceinline__ void suffix_threshold(const unsigned int* sh,
                                                 unsigned int st,
                                                 unsigned int* warp_tot,
                                                 int* out, unsigned int* outAbove) {
    const int t = threadIdx.x, lane = t & 31, wid = t >> 5;
    unsigned int h0 = sh[t * 4], h1 = sh[t * 4 + 1], h2 = sh[t * 4 + 2], h3 = sh[t * 4 + 3];
    unsigned int seg = h0 + h1 + h2 + h3;
    unsigned int suf = seg;
#pragma unroll
    for (int d = 1; d < 32; d <<= 1) {
        unsigned int v = __shfl_down_sync(0xFFFFFFFFu, suf, d);
        if (lane + d < 32) suf += v;
    }
    if (lane == 0) warp_tot[wid] = suf;
    __syncthreads();
    if (wid == 0) {
        unsigned int wv = warp_tot[lane];
        unsigned int wsuf = wv;
#pragma unroll
        for (int d = 1; d < 32; d <<= 1) {
            unsigned int v = __shfl_down_sync(0xFFFFFFFFu, wsuf, d);
            if (lane + d < 32) wsuf += v;
        }
        warp_tot[lane] = wsuf - wv;
    }
    __syncthreads();
    unsigned int S  = suf + warp_tot[wid];
    unsigned int sN = S - seg;
    unsigned int s3 = sN + h3;
    unsigned int s2 = s3 + h2;
    unsigned int s1 = s2 + h1;
    unsigned int s0 = S;
    if      (s3 >= st && sN < st) { *out = t * 4 + 3; *outAbove = sN; }
    else if (s2 >= st && s3 < st) { *out = t * 4 + 2; *outAbove = s3; }
    else if (s1 >= st && s2 < st) { *out = t * 4 + 1; *outAbove = s2; }
    else if (s0 >= st && s1 < st) { *out = t * 4 + 0; *outAbove = s1; }
}

// Exact trim digit from the 64K digit histogram: largest digit d* with
// suffix(d*) >= k. blockDim = 1024; thread t owns digits [64t, 64t+64).
__device__ __forceinline__ void dstar_scan(const unsigned int* h16, unsigned int k,
                                           unsigned int* warp_tot, unsigned int* outD) {
    const int t = threadIdx.x, lane = t & 31, wid = t >> 5;
    unsigned int hl[64];
    unsigned int csum = 0;
    {
        const uint4* hv = (const uint4*)(h16 + t * 64);
#pragma unroll
        for (int q = 0; q < 16; q++) {
            uint4 v = hv[q];
            hl[q * 4 + 0] = v.x; hl[q * 4 + 1] = v.y;
            hl[q * 4 + 2] = v.z; hl[q * 4 + 3] = v.w;
            csum += v.x + v.y + v.z + v.w;
        }
    }
    unsigned int suf = csum;
#pragma unroll
    for (int d = 1; d < 32; d <<= 1) {
        unsigned int v = __shfl_down_sync(0xFFFFFFFFu, suf, d);
        if (lane + d < 32) suf += v;
    }
    if (lane == 0) warp_tot[wid] = suf;
    __syncthreads();
    if (wid == 0) {
        unsigned int wv = warp_tot[lane];
        unsigned int wsuf = wv;
#pragma unroll
        for (int d = 1; d < 32; d <<= 1) {
            unsigned int v = __shfl_down_sync(0xFFFFFFFFu, wsuf, d);
            if (lane + d < 32) wsuf += v;
        }
        warp_tot[lane] = wsuf - wv;
    }
    __syncthreads();
    unsigned int acc = (suf - csum) + warp_tot[wid];   // strictly above thread range
#pragma unroll
    for (int q = 63; q >= 0; q--) {
        unsigned int h = hl[q];
        if (acc < k && acc + h >= k) *outD = (unsigned)(t * 64 + q);
        acc += h;
    }
}

// ---------------------------------------------------------------------------
// K1: 24-bit sampled threshold (1 block/batch). Zeroes replay state.
// ---------------------------------------------------------------------------
__global__ void __launch_bounds__(1024) sample_thresh_kernel(
        const float* __restrict__ scores, int A, int k) {
    __shared__ unsigned int sh[NBINS];
    __shared__ unsigned int warp_tot[32];
    __shared__ int sT1, sT2;
    __shared__ unsigned int sS1, sDummy;
    const int b = blockIdx.x;
    const int t = threadIdx.x;

    for (int i = t; i < NBINS; i += 1024) { sh[i] = 0; g_hist[b * NBINS + i] = 0; }
    if (t == 0) { g_count[b] = 0; g_ctrim[b] = 0; }
    __syncthreads();

    const size_t base = (size_t)b * (size_t)A;
    const int A4 = A >> 2;

    if ((A & 3) == 0 && A4 >= 4096) {
        const float4* s4 = (const float4*)(scores + base);
        unsigned int m[16];
#pragma unroll
        for (int r = 0; r < 4; r++) {
            int j = t + r * 1024;
            size_t pos = ((size_t)j * (size_t)A4) >> 12;
            float4 v = s4[pos];
            m[r * 4 + 0] = mono_f32(v.x);
            m[r * 4 + 1] = mono_f32(v.y);
            m[r * 4 + 2] = mono_f32(v.z);
            m[r * 4 + 3] = mono_f32(v.w);
        }
#pragma unroll
        for (int q = 0; q < 16; q++) atomicAdd(&sh[m[q] >> 20], 1u);
        __syncthreads();

        long long tgt = (16384LL * 7LL * (long long)k) / (4LL * (long long)A);  // ~3.5k
        if (tgt < 1) tgt = 1;
        if (tgt > 16384) tgt = 16384;
        const unsigned int st = (unsigned)tgt;

        suffix_threshold(sh, st, warp_tot, &sT1, &sS1);
        __syncthreads();
        const int T1 = sT1;
        const unsigned int S1 = sS1;
        __syncthreads();

        for (int i = t; i < NBINS; i += 1024) sh[i] = 0;
        __syncthreads();
#pragma unroll
        for (int q = 0; q < 16; q++)
            if ((int)(m[q] >> 20) == T1) atomicAdd(&sh[(m[q] >> 8) & 0xFFFu], 1u);
        __syncthreads();

        suffix_threshold(sh, st - S1, warp_tot, &sT2, &sDummy);
        __syncthreads();
        if (t == 0) g_T24[b] = ((unsigned)T1 << 12) | (unsigned)sT2;
    } else {
        for (int i = t; i < A; i += 1024)
            atomicAdd(&sh[mono_f32(scores[base + i]) >> 20], 1u);
        __syncthreads();
        suffix_threshold(sh, (unsigned)min(k, A), warp_tot, &sT1, &sS1);
        __syncthreads();
        if (t == 0) g_T24[b] = (unsigned)sT1 << 12;
    }
}

// ---------------------------------------------------------------------------
__device__ __forceinline__ void push_warp(int b, bool pred, unsigned long long key) {
    unsigned int bal = __ballot_sync(0xFFFFFFFFu, pred);
    if (!bal) return;
    const int lane = threadIdx.x & 31;
    const int leader = __ffs(bal) - 1;
    int base = 0;
    if (lane == leader) base = atomicAdd(&g_count[b], __popc(bal));
    base = __shfl_sync(0xFFFFFFFFu, base, leader);
    if (pred) {
        int pos = base + __popc(bal & ((1u << lane) - 1u));
        if (pos < CAND_MAX) g_cand[b * CAND_MAX + pos] = key;
        atomicAdd(&g_h16[((size_t)b << 16) + (unsigned)(key >> 48)], 1u);
    }
}

// ---------------------------------------------------------------------------
// K2: single full sweep — compact (m>>8) >= T24 and histogram digits.
// ---------------------------------------------------------------------------
__global__ void __launch_bounds__(HT) compact_kernel(
        const float* __restrict__ scores, int A) {
    const int b = blockIdx.y;
    const unsigned int T24 = g_T24[b];
    const size_t base = (size_t)b * (size_t)A;
    const int lane = threadIdx.x & 31;

    if ((A & 3) == 0) {
        const float4* s4 = (const float4*)(scores + base);
        const int A4 = A >> 2;
        const int warp0 = blockIdx.x * (HT / 32) + (threadIdx.x >> 5);
        for (int i0 = warp0 * 32; i0 < A4; i0 += BPB * HT) {
            const int i = i0 + lane;
            const bool in = i < A4;
            float4 v;
            if (in) v = s4[i];
            unsigned int o = (unsigned)(i << 2);
            unsigned int mx = in ? mono_f32(v.x) : 0u;
            unsigned int my = in ? mono_f32(v.y) : 0u;
            unsigned int mz = in ? mono_f32(v.z) : 0u;
            unsigned int mw = in ? mono_f32(v.w) : 0u;
            push_warp(b, in && (mx >> 8) >= T24,
                      ((unsigned long long)mx << 32) | (0xFFFFFFFFu - (o + 0u)));
            push_warp(b, in && (my >> 8) >= T24,
                      ((unsigned long long)my << 32) | (0xFFFFFFFFu - (o + 1u)));
            push_warp(b, in && (mz >> 8) >= T24,
                      ((unsigned long long)mz << 32) | (0xFFFFFFFFu - (o + 2u)));
            push_warp(b, in && (mw >> 8) >= T24,
                      ((unsigned long long)mw << 32) | (0xFFFFFFFFu - (o + 3u)));
        }
    } else {
        const int warp0 = blockIdx.x * (HT / 32) + (threadIdx.x >> 5);
        for (int i0 = warp0 * 32; i0 < A; i0 += BPB * HT) {
            const int i = i0 + lane;
            const bool in = i < A;
            unsigned int m = in ? mono_f32(scores[base + i]) : 0u;
            push_warp(b, in && (m >> 8) >= T24,
                      ((unsigned long long)m << 32) | (0xFFFFFFFFu - (unsigned)i));
        }
    }
}

// ---------------------------------------------------------------------------
// shared tail for K3: compute d*, reset only the nonzero h16 digits (one per
// stored candidate), compact trimmed keys to g_trim. ONE 1024-thr block/batch.
// ---------------------------------------------------------------------------
__device__ __forceinline__ void trim_finish(int b, int A, int k,
                                            unsigned int* warp_tot,
                                            unsigned int* sD) {
    const int t = threadIdx.x;
    unsigned int* h16 = &g_h16[(size_t)b << 16];
    dstar_scan(h16, (unsigned)min(k, A), warp_tot, sD);
    __syncthreads();
    const unsigned int dstar = *sD;

    const int Ct = min(g_count[b], CAND_MAX);
    const unsigned long long* cand = &g_cand[(size_t)b * CAND_MAX];
    unsigned long long* trim = &g_trim[(size_t)b * CAND_MAX];
    const int lane = t & 31;

    // sparse reset: every nonzero digit belongs to some stored candidate
    // (success path never overflows CAND_MAX; fallback recompact <= ~6k)
    for (int i = t; i < Ct; i += 1024)
        h16[(unsigned)(cand[i] >> 48)] = 0;

    for (int i0 = (t & ~31); i0 < Ct; i0 += 1024) {
        const int i = i0 + lane;
        const bool in = i < Ct;
        unsigned long long key = in ? cand[i] : 0ull;
        bool pred = in && (unsigned)(key >> 48) >= dstar;
        unsigned int bal = __ballot_sync(0xFFFFFFFFu, pred);
        if (!bal) continue;
        int basep = 0;
        const int leader = __ffs(bal) - 1;
        if (lane == leader) basep = atomicAdd(&g_ctrim[b], __popc(bal));
        basep = __shfl_sync(0xFFFFFFFFu, basep, leader);
        if (pred) {
            int pos = basep + __popc(bal & ((1u << lane) - 1u));
            if (pos < CAND_MAX) trim[pos] = key;
        }
    }
}

// ---------------------------------------------------------------------------
// K3: success path -> block 0 trims. Fallback (~never): exact hist sweep;
// finisher re-thresholds, recompacts alone, then trims. grid (BPB, N) x 1024
// ---------------------------------------------------------------------------
__global__ void __launch_bounds__(1024) fb_kernel(
        const float* __restrict__ scores, int A, int k) {
    const int b = blockIdx.y;
    const int t = threadIdx.x;
    __shared__ unsigned int warp_tot[32];
    __shared__ unsigned int sD;
    unsigned int* h16 = &g_h16[(size_t)b << 16];

    {
        const int c = g_count[b];
        if (c >= min(k, A) && c <= CAND_MAX) {
            if (blockIdx.x != 0) return;
            trim_finish(b, A, k, warp_tot, &sD);
            return;
        }
    }
    __shared__ unsigned int sh[NBINS];
    __shared__ int sT;
    __shared__ unsigned int sAb;
    __shared__ bool s_last;
    const size_t base = (size_t)b * (size_t)A;

    for (int i = t; i < NBINS; i += 1024) sh[i] = 0;
    __syncthreads();
    for (int i = blockIdx.x * 1024 + t; i < A; i += BPB * 1024)
        atomicAdd(&sh[mono_f32(scores[base + i]) >> 20], 1u);
    __syncthreads();
    for (int i = t; i < NBINS; i += 1024) {
        unsigned int c = sh[i];
        if (c) atomicAdd(&g_hist[b * NBINS + i], c);
    }
    __threadfence();
    __syncthreads();
    if (t == 0) s_last = (atomicAdd(&g_done1[b], 1u) == (unsigned)gridDim.x - 1u);
    __syncthreads();
    if (!s_last) return;
    if (t == 0) g_done1[b] = 0;

    for (int i = t; i < NBINS; i += 1024) sh[i] = g_hist[b * NBINS + i];
    __syncthreads();
    suffix_threshold(sh, (unsigned)min(k, A), warp_tot, &sT, &sAb);
    __syncthreads();
    const unsigned int T24 = (unsigned)sT << 12;
    if (t == 0) { g_T24[b] = T24; g_count[b] = 0; g_ctrim[b] = 0; }
    for (int i = t; i < 65536; i += 1024) h16[i] = 0;   // full reset (pathological path)
    __syncthreads();

    for (int i = t; i < A; i += 1024) {
        unsigned int m = mono_f32(scores[base + i]);
        if ((m >> 8) >= T24) {
            unsigned long long key = ((unsigned long long)m << 32) |
                                     (unsigned long long)(0xFFFFFFFFu - (unsigned)i);
            int p = atomicAdd(&g_count[b], 1);
            if (p < CAND_MAX) g_cand[b * CAND_MAX + p] = key;
            atomicAdd(&h16[(unsigned)(key >> 48)], 1u);
        }
    }
    __syncthreads();
    trim_finish(b, A, k, warp_tot, &sD);
}

// ---------------------------------------------------------------------------
// decode one key at output rank r
// ---------------------------------------------------------------------------
__device__ __forceinline__ void decode_one(unsigned long long key, int r,
                                           const float* __restrict__ anchors,
                                           const float* __restrict__ breg,
                                           float* __restrict__ out,
                                           size_t base, int b, int k) {
    const float CLIP = 4.135166556742356f;   // log(1000/16)
    unsigned int idx = 0xFFFFFFFFu - (unsigned int)(key & 0xFFFFFFFFull);
    float sc = inv_mono((unsigned int)(key >> 32));
    size_t g4 = (base + (size_t)idx) * 4;

    float4 box = *(const float4*)(anchors + g4);
    float4 rc  = *(const float4*)(breg + g4);

    float w  = box.z - box.x + 1.0f;
    float h  = box.w - box.y + 1.0f;
    float cx = box.x + 0.5f * w;
    float cy = box.y + 0.5f * h;

    float dw = fminf(rc.z, CLIP);
    float dh = fminf(rc.w, CLIP);

    float pcx = rc.x * w + cx;
    float pcy = rc.y * h + cy;
    float pw  = expf(dw) * w;
    float ph  = expf(dh) * h;

    float* o = out + ((size_t)b * k + r) * 5;
    o[0] = pcx - 0.5f * pw;
    o[1] = pcy - 0.5f * ph;
    o[2] = pcx + 0.5f * pw - 1.0f;
    o[3] = pcy + 0.5f * ph - 1.0f;
    o[4] = sc;
}

// ---------------------------------------------------------------------------
// K4: warp-per-4-candidates rank + decode over the trimmed set (ranks within
// the trimmed set are exact global ranks). grid (32, N) x 512, 32 KB smem.
// ---------------------------------------------------------------------------
__global__ void __launch_bounds__(512) rank_decode_kernel(
        const float* __restrict__ anchors,
        const float* __restrict__ breg,
        float* __restrict__ out,
        int A, int k) {
    __shared__ unsigned long long tile[TRIM_TILE];
    const int b = blockIdx.y;
    const int t = threadIdx.x;
    const int lane = t & 31;
    const int gw = blockIdx.x * (512 / 32) + (t >> 5);   // global warp id
    const int NW = gridDim.x * (512 / 32);               // warps per batch
    const int Ctr = min(g_ctrim[b], CAND_MAX);
    const unsigned long long* trim = &g_trim[(size_t)b * CAND_MAX];
    const size_t base = (size_t)b * (size_t)A;

    const bool fits = (Ctr <= TRIM_TILE);
    if (fits) {
        for (int i = t; i < Ctr; i += 512) tile[i] = trim[i];
        __syncthreads();
    }
    const unsigned long long* keys = fits ? tile : trim;

    for (int c0 = gw * 4; c0 < Ctr; c0 += NW * 4) {
        unsigned long long k0 = keys[c0];
        unsigned long long k1 = (c0 + 1 < Ctr) ? keys[c0 + 1] : ~0ull;
        unsigned long long k2 = (c0 + 2 < Ctr) ? keys[c0 + 2] : ~0ull;
        unsigned long long k3 = (c0 + 3 < Ctr) ? keys[c0 + 3] : ~0ull;
        int r0 = 0, r1 = 0, r2 = 0, r3 = 0;
        for (int j = lane; j < Ctr; j += 32) {
            unsigned long long kj = keys[j];
            r0 += (kj > k0);
            r1 += (kj > k1);
            r2 += (kj > k2);
            r3 += (kj > k3);
        }
#pragma unroll
        for (int d = 16; d >= 1; d >>= 1) {
            r0 += __shfl_down_sync(0xFFFFFFFFu, r0, d);
            r1 += __shfl_down_sync(0xFFFFFFFFu, r1, d);
            r2 += __shfl_down_sync(0xFFFFFFFFu, r2, d);
            r3 += __shfl_down_sync(0xFFFFFFFFu, r3, d);
        }
        if (lane == 0) {
            if (r0 < k)                  decode_one(k0, r0, anchors, breg, out, base, b, k);
            if (c0 + 1 < Ctr && r1 < k)  decode_one(k1, r1, anchors, breg, out, base, b, k);
            if (c0 + 2 < Ctr && r2 < k)  decode_one(k2, r2, anchors, breg, out, base, b, k);
            if (c0 + 3 < Ctr && r3 < k)  decode_one(k3, r3, anchors, breg, out, base, b, k);
        }
    }
}

// ---------------------------------------------------------------------------
extern "C" void kernel_launch(void* const* d_in, const int* in_sizes, int n_in,
                              void* d_out, int out_size) {
    const float* anchors    = (const float*)d_in[0];
    const float* objectness = (const float*)d_in[1];
    const float* breg       = (const float*)d_in[2];
    float* out = (float*)d_out;

    const int NA = in_sizes[1];
    const int k  = 2000;
    const int N  = out_size / (k * 5);
    const int A  = NA / N;

    sample_thresh_kernel<<<N, 1024>>>(objectness, A, k);
    compact_kernel<<<dim3(BPB, N), HT>>>(objectness, A);
    fb_kernel<<<dim3(BPB, N), 1024>>>(objectness, A, k);
    rank_decode_kernel<<<dim3(32, N), 512>>>(anchors, breg, out, A, k);
}